// round 6
// baseline (speedup 1.0000x reference)
#include <cuda_runtime.h>

// GCN: h1 = relu(GCNConv(x, W1, b1)); h2 = GCNConv(h1, W2, b2);
// g = segment_sum(h2, batch); out = log_softmax(g @ Wlin + blin)
//
// out[c] = dinv[c] * ( sum_{e: col=c} hs[row] + hs[c] ) + b,  hs = (x@W)*dinv.
// CSR bucketed on device -> edge slots sorted by target. Propagation is
// edge-slot-parallel: warp = 8 slots x 4 feature lanes, shuffle segmented
// reduction by target, red.v4 only at run boundaries (load-balanced).

static const int NN = 100000;
static const int NG = 1024;
static const int EMAX = 3200000;
static const int NBLK = (NN + 255) / 256;   // 391 scan blocks

// Scratch (device globals; no allocation allowed)
__device__ int    g_is64;
__device__ int    g_batch32[NN];
__device__ int    g_degi[NN];
__device__ int    g_start[NN + 1];
__device__ int    g_cursor[NN];
__device__ int    g_bsum[NBLK];
__device__ int    g_boff[NBLK];
__device__ int2   g_pairs[EMAX];       // (src, tgt) per bucketed slot
__device__ __align__(16) float g_dinv[NN];
__device__ float4 g_hs1[NN * 4];
__device__ float4 g_hs2[NN * 4];
__device__ float4 g_t1 [NN * 4];
__device__ float4 g_t2 [NN * 4];
__device__ float4 g_pool[NG * 4];

__device__ __forceinline__ void red_add_v4(float* addr, float4 v) {
    asm volatile("red.global.add.v4.f32 [%0], {%1, %2, %3, %4};"
                 :: "l"(addr), "f"(v.x), "f"(v.y), "f"(v.z), "f"(v.w)
                 : "memory");
}

// ---------------------------------------------------------------------------
// 1) init: zero deg/t1/t2/pool; dtype detect in block 0
__global__ void k_init(const void* __restrict__ ei, int twoE) {
    int i = blockIdx.x * blockDim.x + threadIdx.x;
    float4 z = make_float4(0.f, 0.f, 0.f, 0.f);
    if (i < NN * 4) { g_t1[i] = z; g_t2[i] = z; }
    if (i < NN) g_degi[i] = 0;
    if (i < NG * 4) g_pool[i] = z;
    if (blockIdx.x == 0) {
        __shared__ int bad;
        if (threadIdx.x == 0) bad = 0;
        __syncthreads();
        const long long* p64 = (const long long*)ei;
        int n = twoE / 2 < 2048 ? twoE / 2 : 2048;
        for (int k = threadIdx.x; k < n; k += blockDim.x) {
            unsigned long long v = (unsigned long long)p64[k];
            if (v >> 32) bad = 1;   // benign race
        }
        __syncthreads();
        if (threadIdx.x == 0) g_is64 = bad ? 0 : 1;
    }
}

// 2) degree count over raw cols + batch conversion
__global__ void k_deg(const void* __restrict__ ei, const void* __restrict__ batch,
                      int E) {
    int i = blockIdx.x * blockDim.x + threadIdx.x;
    int is64 = g_is64;
    if (i < E) {
        int c = is64 ? (int)((const long long*)ei)[E + i]
                     : ((const int*)ei)[E + i];
        atomicAdd(&g_degi[c], 1);
    }
    if (i < NN) {
        g_batch32[i] = is64 ? (int)((const long long*)batch)[i]
                            : ((const int*)batch)[i];
    }
}

// 3) prefix scan of degrees -> CSR starts
__global__ void k_scanA() {
    __shared__ int sh[256];
    int t = threadIdx.x;
    int i = blockIdx.x * 256 + t;
    sh[t] = (i < NN) ? g_degi[i] : 0;
    __syncthreads();
    for (int off = 128; off > 0; off >>= 1) {
        if (t < off) sh[t] += sh[t + off];
        __syncthreads();
    }
    if (t == 0) g_bsum[blockIdx.x] = sh[0];
}

__global__ void k_scanB() {
    __shared__ int sh[512];
    int t = threadIdx.x;
    int v = (t < NBLK) ? g_bsum[t] : 0;
    sh[t] = v;
    __syncthreads();
    for (int off = 1; off < 512; off <<= 1) {
        int a = (t >= off) ? sh[t - off] : 0;
        __syncthreads();
        sh[t] += a;
        __syncthreads();
    }
    if (t < NBLK) g_boff[t] = sh[t] - v;
    if (t == NBLK - 1) g_start[NN] = sh[t];
}

__global__ void k_scanC() {
    __shared__ int sh[256];
    int t = threadIdx.x;
    int i = blockIdx.x * 256 + t;
    int v = (i < NN) ? g_degi[i] : 0;
    sh[t] = v;
    __syncthreads();
    for (int off = 1; off < 256; off <<= 1) {
        int add = (t >= off) ? sh[t - off] : 0;
        __syncthreads();
        sh[t] += add;
        __syncthreads();
    }
    if (i < NN) {
        int excl = g_boff[blockIdx.x] + sh[t] - v;
        g_start[i]  = excl;
        g_cursor[i] = excl;
        g_dinv[i]   = rsqrtf((float)(v + 1));   // +1 self loop
    }
}

// 4) bucket: slot[pos] = (src, tgt), sorted by tgt via cursor
__global__ void k_bucket(const void* __restrict__ ei, int E) {
    int e = blockIdx.x * blockDim.x + threadIdx.x;
    if (e >= E) return;
    int r, c;
    if (g_is64) {
        r = (int)((const long long*)ei)[e];
        c = (int)((const long long*)ei)[E + e];
    } else {
        r = ((const int*)ei)[e];
        c = ((const int*)ei)[E + e];
    }
    int pos = atomicAdd(&g_cursor[c], 1);
    g_pairs[pos] = make_int2(r, c);
}

// 5) hs1 = (x @ W1) * dinv
__global__ void k_hs1(const float* __restrict__ x, const float* __restrict__ W1) {
    __shared__ float sW[48];
    if (threadIdx.x < 48) sW[threadIdx.x] = W1[threadIdx.x];
    __syncthreads();
    int i = blockIdx.x * blockDim.x + threadIdx.x;
    if (i >= NN) return;
    float x0 = __ldg(x + 3 * i + 0);
    float x1 = __ldg(x + 3 * i + 1);
    float x2 = __ldg(x + 3 * i + 2);
    float di = g_dinv[i];
    float h[16];
#pragma unroll
    for (int j = 0; j < 16; j++)
        h[j] = di * (x0 * sW[j] + x1 * sW[16 + j] + x2 * sW[32 + j]);
    float4* dst = &g_hs1[i * 4];
    dst[0] = make_float4(h[0],  h[1],  h[2],  h[3]);
    dst[1] = make_float4(h[4],  h[5],  h[6],  h[7]);
    dst[2] = make_float4(h[8],  h[9],  h[10], h[11]);
    dst[3] = make_float4(h[12], h[13], h[14], h[15]);
}

// 6) edge-slot-parallel accumulate: t[tgt] += hs[src], segmented by tgt.
//    Warp = 8 slots x 4 q-lanes (lane = 4*group + q).
template <int LAYER>
__global__ void k_acc(int E) {
    int warp = (blockIdx.x * blockDim.x + threadIdx.x) >> 5;
    int lane = threadIdx.x & 31;
    int gr = lane >> 2;
    int q  = lane & 3;
    int slot = warp * 8 + gr;
    const float4* hs = (LAYER == 0) ? g_hs1 : g_hs2;
    float4*       t  = (LAYER == 0) ? g_t1  : g_t2;
    int tgt = -1;
    float4 val = make_float4(0.f, 0.f, 0.f, 0.f);
    if (slot < E) {
        int2 pr = __ldg(&g_pairs[slot]);
        tgt = pr.y;
        val = __ldg(hs + pr.x * 4 + q);
    }
    // segmented inclusive scan across the 8 groups (stride in lanes = 4*d)
#pragma unroll
    for (int d = 1; d < 8; d <<= 1) {
        int ot = __shfl_up_sync(0xffffffff, tgt, 4 * d);
        float ox = __shfl_up_sync(0xffffffff, val.x, 4 * d);
        float oy = __shfl_up_sync(0xffffffff, val.y, 4 * d);
        float oz = __shfl_up_sync(0xffffffff, val.z, 4 * d);
        float ow = __shfl_up_sync(0xffffffff, val.w, 4 * d);
        if (gr >= d && ot == tgt) {
            val.x += ox; val.y += oy; val.z += oz; val.w += ow;
        }
    }
    int nt = __shfl_down_sync(0xffffffff, tgt, 4);
    bool last = (gr == 7) || (nt != tgt);
    if (slot < E && last)
        red_add_v4((float*)(t + tgt * 4 + q), val);
}

// 7) layer1 epilogue: v = relu(dinv*(t1+hs1)+b1); hs2 = (v@W2)*dinv
//    4 lanes/node; 16x16 matmul via warp shuffles.
__global__ void k_epi1(const float* __restrict__ b1, const float* __restrict__ W2) {
    __shared__ float sW[256];
    __shared__ float sb[16];
    if (threadIdx.x < 256) sW[threadIdx.x] = W2[threadIdx.x];
    if (threadIdx.x < 16)  sb[threadIdx.x] = b1[threadIdx.x];
    __syncthreads();
    int t = blockIdx.x * blockDim.x + threadIdx.x;
    int node = t >> 2;
    int q = t & 3;
    if (node >= NN) return;
    float4 tv = g_t1[node * 4 + q];
    float4 hv = __ldg(&g_hs1[node * 4 + q]);
    float di = g_dinv[node];
    float4 myv;
    myv.x = fmaxf(fmaf(di, tv.x + hv.x, sb[q * 4 + 0]), 0.f);
    myv.y = fmaxf(fmaf(di, tv.y + hv.y, sb[q * 4 + 1]), 0.f);
    myv.z = fmaxf(fmaf(di, tv.z + hv.z, sb[q * 4 + 2]), 0.f);
    myv.w = fmaxf(fmaf(di, tv.w + hv.w, sb[q * 4 + 3]), 0.f);
    int lane = threadIdx.x & 31;
    int base = lane & ~3;
    float o0 = 0.f, o1 = 0.f, o2 = 0.f, o3 = 0.f;
#pragma unroll
    for (int p = 0; p < 4; p++) {
        float4 vp;
        vp.x = __shfl_sync(0xffffffff, myv.x, base + p);
        vp.y = __shfl_sync(0xffffffff, myv.y, base + p);
        vp.z = __shfl_sync(0xffffffff, myv.z, base + p);
        vp.w = __shfl_sync(0xffffffff, myv.w, base + p);
        const float* w0 = &sW[(p * 4 + 0) * 16 + q * 4];
        const float* w1 = &sW[(p * 4 + 1) * 16 + q * 4];
        const float* w2 = &sW[(p * 4 + 2) * 16 + q * 4];
        const float* w3 = &sW[(p * 4 + 3) * 16 + q * 4];
        o0 = fmaf(vp.x, w0[0], fmaf(vp.y, w1[0], fmaf(vp.z, w2[0], fmaf(vp.w, w3[0], o0))));
        o1 = fmaf(vp.x, w0[1], fmaf(vp.y, w1[1], fmaf(vp.z, w2[1], fmaf(vp.w, w3[1], o1))));
        o2 = fmaf(vp.x, w0[2], fmaf(vp.y, w1[2], fmaf(vp.z, w2[2], fmaf(vp.w, w3[2], o2))));
        o3 = fmaf(vp.x, w0[3], fmaf(vp.y, w1[3], fmaf(vp.z, w2[3], fmaf(vp.w, w3[3], o3))));
    }
    g_hs2[node * 4 + q] = make_float4(di * o0, di * o1, di * o2, di * o3);
}

// 8) layer2 epilogue: h2 = dinv*(t2+hs2)+b2; pool[batch] += h2
__global__ void k_epi2(const float* __restrict__ b2) {
    __shared__ float sb[16];
    if (threadIdx.x < 16) sb[threadIdx.x] = b2[threadIdx.x];
    __syncthreads();
    int t = blockIdx.x * blockDim.x + threadIdx.x;
    int node = t >> 2;
    int q = t & 3;
    if (node >= NN) return;
    float4 tv = g_t2[node * 4 + q];
    float4 hv = __ldg(&g_hs2[node * 4 + q]);
    float di = g_dinv[node];
    int g = g_batch32[node];
    float4 r;
    r.x = fmaf(di, tv.x + hv.x, sb[q * 4 + 0]);
    r.y = fmaf(di, tv.y + hv.y, sb[q * 4 + 1]);
    r.z = fmaf(di, tv.z + hv.z, sb[q * 4 + 2]);
    r.w = fmaf(di, tv.w + hv.w, sb[q * 4 + 3]);
    red_add_v4((float*)&g_pool[g * 4 + q], r);
}

// 9) per-graph head: logits = pool @ Wlin + blin; log_softmax
__global__ void k_logits(const float* __restrict__ Wlin, const float* __restrict__ blin,
                         float* __restrict__ out) {
    int g = blockIdx.x * blockDim.x + threadIdx.x;
    if (g >= NG) return;
    float gv[16];
#pragma unroll
    for (int q = 0; q < 4; q++) {
        float4 p = g_pool[g * 4 + q];
        gv[q * 4 + 0] = p.x; gv[q * 4 + 1] = p.y;
        gv[q * 4 + 2] = p.z; gv[q * 4 + 3] = p.w;
    }
    float lg[7];
#pragma unroll
    for (int o = 0; o < 7; o++) {
        float acc = __ldg(blin + o);
#pragma unroll
        for (int k = 0; k < 16; k++)
            acc = fmaf(gv[k], __ldg(Wlin + k * 7 + o), acc);
        lg[o] = acc;
    }
    float m = lg[0];
#pragma unroll
    for (int o = 1; o < 7; o++) m = fmaxf(m, lg[o]);
    float s = 0.f;
#pragma unroll
    for (int o = 0; o < 7; o++) s += expf(lg[o] - m);
    float ls = logf(s) + m;
#pragma unroll
    for (int o = 0; o < 7; o++) out[g * 7 + o] = lg[o] - ls;
}

// ---------------------------------------------------------------------------
extern "C" void kernel_launch(void* const* d_in, const int* in_sizes, int n_in,
                              void* d_out, int out_size) {
    int p = 0;
    const float* x     = (const float*)d_in[p]; p++;
    const void*  ei    = d_in[p];
    int twoE = in_sizes[p];
    int E = twoE / 2; p++;
    const void*  batch = d_in[p]; p++;
    if (p < n_in && in_sizes[p] == 1) p++;  // skip scalar num_graphs if present
    const float* W1   = (const float*)d_in[p]; p++;
    const float* b1   = (const float*)d_in[p]; p++;
    const float* W2   = (const float*)d_in[p]; p++;
    const float* b2   = (const float*)d_in[p]; p++;
    const float* Wlin = (const float*)d_in[p]; p++;
    const float* blin = (const float*)d_in[p]; p++;
    float* out = (float*)d_out;

    const int TB = 256;
    int gN  = (NN + TB - 1) / TB;
    int gN4 = (NN * 4 + TB - 1) / TB;
    int gE  = (E + TB - 1) / TB;
    int nWarps = (E + 7) / 8;
    int gAcc = (nWarps * 32 + TB - 1) / TB;

    k_init    <<<gN4, TB>>>(ei, twoE);
    k_deg     <<<gE,  TB>>>(ei, batch, E);
    k_scanA   <<<NBLK, TB>>>();
    k_scanB   <<<1,   512>>>();
    k_scanC   <<<NBLK, TB>>>();
    k_bucket  <<<gE,  TB>>>(ei, E);
    k_hs1     <<<gN,  TB>>>(x, W1);
    k_acc<0>  <<<gAcc, TB>>>(E);
    k_epi1    <<<gN4, TB>>>(b1, W2);
    k_acc<1>  <<<gAcc, TB>>>(E);
    k_epi2    <<<gN4, TB>>>(b2);
    k_logits  <<<(NG + TB - 1) / TB, TB>>>(Wlin, blin, out);
}

// round 7
// speedup vs baseline: 1.4610x; 1.4610x over previous
#include <cuda_runtime.h>

// GCN: h1 = relu(GCNConv(x, W1, b1)); h2 = GCNConv(h1, W2, b2);
// g = segment_sum(h2, batch); out = log_softmax(g @ Wlin + blin)
//
// out[c] = dinv[c] * ( sum_{e: col=c} hs[row] + hs[c] ) + b,  hs = (x@W)*dinv.
// CSR built on device; propagation = node-parallel gather, 4 lanes/node
// (one float4 quarter each), software-pipelined 8 edges deep for MLP.

static const int NN = 100000;
static const int NG = 1024;
static const int EMAX = 3200000;
static const int NBLK = (NN + 255) / 256;   // 391 scan blocks

// Scratch (device globals; no allocation allowed)
__device__ int    g_is64;
__device__ int    g_batch32[NN];
__device__ int    g_degi[NN];
__device__ int    g_start[NN + 1];
__device__ int    g_cursor[NN];
__device__ int    g_bsum[NBLK];
__device__ int    g_boff[NBLK];
__device__ int    g_srcs[EMAX];
__device__ __align__(16) float g_dinv[NN];
__device__ float4 g_hs1[NN * 4];
__device__ float4 g_hs2[NN * 4];
__device__ float4 g_pool[NG * 4];

__device__ __forceinline__ void red_add_v4(float* addr, float4 v) {
    asm volatile("red.global.add.v4.f32 [%0], {%1, %2, %3, %4};"
                 :: "l"(addr), "f"(v.x), "f"(v.y), "f"(v.z), "f"(v.w)
                 : "memory");
}

__device__ __forceinline__ void acc4(float4& a, const float4 b) {
    a.x += b.x; a.y += b.y; a.z += b.z; a.w += b.w;
}

// ---------------------------------------------------------------------------
// 1) init: zero deg + pool; dtype detect in block 0
__global__ void k_init(const void* __restrict__ ei, int twoE) {
    int i = blockIdx.x * blockDim.x + threadIdx.x;
    if (i < NN) g_degi[i] = 0;
    if (i < NG * 4) g_pool[i] = make_float4(0.f, 0.f, 0.f, 0.f);
    if (blockIdx.x == 0) {
        __shared__ int bad;
        if (threadIdx.x == 0) bad = 0;
        __syncthreads();
        const long long* p64 = (const long long*)ei;
        int n = twoE / 2 < 2048 ? twoE / 2 : 2048;
        for (int k = threadIdx.x; k < n; k += blockDim.x) {
            unsigned long long v = (unsigned long long)p64[k];
            if (v >> 32) bad = 1;   // benign race
        }
        __syncthreads();
        if (threadIdx.x == 0) g_is64 = bad ? 0 : 1;
    }
}

// 2) degree count over raw cols + fused batch conversion
__global__ void k_deg(const void* __restrict__ ei, const void* __restrict__ batch,
                      int E) {
    int i = blockIdx.x * blockDim.x + threadIdx.x;
    int is64 = g_is64;
    if (i < E) {
        int c = is64 ? (int)((const long long*)ei)[E + i]
                     : ((const int*)ei)[E + i];
        atomicAdd(&g_degi[c], 1);
    }
    if (i < NN) {
        g_batch32[i] = is64 ? (int)((const long long*)batch)[i]
                            : ((const int*)batch)[i];
    }
}

// 3) prefix scan of degrees -> CSR starts
__global__ void k_scanA() {
    __shared__ int sh[256];
    int t = threadIdx.x;
    int i = blockIdx.x * 256 + t;
    sh[t] = (i < NN) ? g_degi[i] : 0;
    __syncthreads();
    for (int off = 128; off > 0; off >>= 1) {
        if (t < off) sh[t] += sh[t + off];
        __syncthreads();
    }
    if (t == 0) g_bsum[blockIdx.x] = sh[0];
}

__global__ void k_scanB() {
    __shared__ int sh[512];
    int t = threadIdx.x;
    int v = (t < NBLK) ? g_bsum[t] : 0;
    sh[t] = v;
    __syncthreads();
    for (int off = 1; off < 512; off <<= 1) {
        int a = (t >= off) ? sh[t - off] : 0;
        __syncthreads();
        sh[t] += a;
        __syncthreads();
    }
    if (t < NBLK) g_boff[t] = sh[t] - v;
    if (t == NBLK - 1) g_start[NN] = sh[t];
}

__global__ void k_scanC() {
    __shared__ int sh[256];
    int t = threadIdx.x;
    int i = blockIdx.x * 256 + t;
    int v = (i < NN) ? g_degi[i] : 0;
    sh[t] = v;
    __syncthreads();
    for (int off = 1; off < 256; off <<= 1) {
        int add = (t >= off) ? sh[t - off] : 0;
        __syncthreads();
        sh[t] += add;
        __syncthreads();
    }
    if (i < NN) {
        int excl = g_boff[blockIdx.x] + sh[t] - v;
        g_start[i]  = excl;
        g_cursor[i] = excl;
        g_dinv[i]   = rsqrtf((float)(v + 1));   // +1 self loop
    }
}

// 4) bucket edge sources by target (raw reads, 4B scatter writes)
__global__ void k_bucket(const void* __restrict__ ei, int E) {
    int e = blockIdx.x * blockDim.x + threadIdx.x;
    if (e >= E) return;
    int r, c;
    if (g_is64) {
        r = (int)((const long long*)ei)[e];
        c = (int)((const long long*)ei)[E + e];
    } else {
        r = ((const int*)ei)[e];
        c = ((const int*)ei)[E + e];
    }
    int pos = atomicAdd(&g_cursor[c], 1);
    g_srcs[pos] = r;
}

// 5) hs1 = (x @ W1) * dinv
__global__ void k_hs1(const float* __restrict__ x, const float* __restrict__ W1) {
    __shared__ float sW[48];
    if (threadIdx.x < 48) sW[threadIdx.x] = W1[threadIdx.x];
    __syncthreads();
    int i = blockIdx.x * blockDim.x + threadIdx.x;
    if (i >= NN) return;
    float x0 = __ldg(x + 3 * i + 0);
    float x1 = __ldg(x + 3 * i + 1);
    float x2 = __ldg(x + 3 * i + 2);
    float di = g_dinv[i];
    float h[16];
#pragma unroll
    for (int j = 0; j < 16; j++)
        h[j] = di * (x0 * sW[j] + x1 * sW[16 + j] + x2 * sW[32 + j]);
    float4* dst = &g_hs1[i * 4];
    dst[0] = make_float4(h[0],  h[1],  h[2],  h[3]);
    dst[1] = make_float4(h[4],  h[5],  h[6],  h[7]);
    dst[2] = make_float4(h[8],  h[9],  h[10], h[11]);
    dst[3] = make_float4(h[12], h[13], h[14], h[15]);
}

// shared gather body: 8-deep software pipeline (indices, then 8 independent
// float4 gathers), tail scalar.
__device__ __forceinline__ float4 gather_q(const float4* __restrict__ hs,
                                           int node, int q) {
    float4 acc = __ldg(hs + node * 4 + q);
    int e  = g_start[node];
    int e2 = g_start[node + 1];
    for (; e + 8 <= e2; e += 8) {
        int r0 = __ldg(&g_srcs[e + 0]);
        int r1 = __ldg(&g_srcs[e + 1]);
        int r2 = __ldg(&g_srcs[e + 2]);
        int r3 = __ldg(&g_srcs[e + 3]);
        int r4 = __ldg(&g_srcs[e + 4]);
        int r5 = __ldg(&g_srcs[e + 5]);
        int r6 = __ldg(&g_srcs[e + 6]);
        int r7 = __ldg(&g_srcs[e + 7]);
        float4 v0 = __ldg(hs + r0 * 4 + q);
        float4 v1 = __ldg(hs + r1 * 4 + q);
        float4 v2 = __ldg(hs + r2 * 4 + q);
        float4 v3 = __ldg(hs + r3 * 4 + q);
        float4 v4 = __ldg(hs + r4 * 4 + q);
        float4 v5 = __ldg(hs + r5 * 4 + q);
        float4 v6 = __ldg(hs + r6 * 4 + q);
        float4 v7 = __ldg(hs + r7 * 4 + q);
        acc4(acc, v0); acc4(acc, v1); acc4(acc, v2); acc4(acc, v3);
        acc4(acc, v4); acc4(acc, v5); acc4(acc, v6); acc4(acc, v7);
    }
    for (; e < e2; e++) {
        int r = __ldg(&g_srcs[e]);
        acc4(acc, __ldg(hs + r * 4 + q));
    }
    return acc;
}

// 6) layer1: gather + relu + 16x16 matmul via warp shuffles
__global__ void k_layer1(const float* __restrict__ b1, const float* __restrict__ W2) {
    __shared__ float sW[256];
    __shared__ float sb[16];
    if (threadIdx.x < 256) sW[threadIdx.x] = W2[threadIdx.x];
    if (threadIdx.x < 16)  sb[threadIdx.x] = b1[threadIdx.x];
    __syncthreads();
    int t = blockIdx.x * blockDim.x + threadIdx.x;
    int node = t >> 2;
    int q = t & 3;
    if (node >= NN) return;
    float4 acc = gather_q(g_hs1, node, q);
    float di = g_dinv[node];
    float4 myv;
    myv.x = fmaxf(fmaf(di, acc.x, sb[q * 4 + 0]), 0.f);
    myv.y = fmaxf(fmaf(di, acc.y, sb[q * 4 + 1]), 0.f);
    myv.z = fmaxf(fmaf(di, acc.z, sb[q * 4 + 2]), 0.f);
    myv.w = fmaxf(fmaf(di, acc.w, sb[q * 4 + 3]), 0.f);
    int lane = threadIdx.x & 31;
    int base = lane & ~3;
    float o0 = 0.f, o1 = 0.f, o2 = 0.f, o3 = 0.f;
#pragma unroll
    for (int p = 0; p < 4; p++) {
        float4 vp;
        vp.x = __shfl_sync(0xffffffff, myv.x, base + p);
        vp.y = __shfl_sync(0xffffffff, myv.y, base + p);
        vp.z = __shfl_sync(0xffffffff, myv.z, base + p);
        vp.w = __shfl_sync(0xffffffff, myv.w, base + p);
        const float* w0 = &sW[(p * 4 + 0) * 16 + q * 4];
        const float* w1 = &sW[(p * 4 + 1) * 16 + q * 4];
        const float* w2 = &sW[(p * 4 + 2) * 16 + q * 4];
        const float* w3 = &sW[(p * 4 + 3) * 16 + q * 4];
        o0 = fmaf(vp.x, w0[0], fmaf(vp.y, w1[0], fmaf(vp.z, w2[0], fmaf(vp.w, w3[0], o0))));
        o1 = fmaf(vp.x, w0[1], fmaf(vp.y, w1[1], fmaf(vp.z, w2[1], fmaf(vp.w, w3[1], o1))));
        o2 = fmaf(vp.x, w0[2], fmaf(vp.y, w1[2], fmaf(vp.z, w2[2], fmaf(vp.w, w3[2], o2))));
        o3 = fmaf(vp.x, w0[3], fmaf(vp.y, w1[3], fmaf(vp.z, w2[3], fmaf(vp.w, w3[3], o3))));
    }
    g_hs2[node * 4 + q] = make_float4(di * o0, di * o1, di * o2, di * o3);
}

// 7) layer2: gather + bias + pool reduction
__global__ void k_layer2(const float* __restrict__ b2) {
    __shared__ float sb[16];
    if (threadIdx.x < 16) sb[threadIdx.x] = b2[threadIdx.x];
    __syncthreads();
    int t = blockIdx.x * blockDim.x + threadIdx.x;
    int node = t >> 2;
    int q = t & 3;
    if (node >= NN) return;
    float4 acc = gather_q(g_hs2, node, q);
    float di = g_dinv[node];
    int g = g_batch32[node];
    float4 r;
    r.x = fmaf(di, acc.x, sb[q * 4 + 0]);
    r.y = fmaf(di, acc.y, sb[q * 4 + 1]);
    r.z = fmaf(di, acc.z, sb[q * 4 + 2]);
    r.w = fmaf(di, acc.w, sb[q * 4 + 3]);
    red_add_v4((float*)&g_pool[g * 4 + q], r);
}

// 8) per-graph head: logits = pool @ Wlin + blin; log_softmax
__global__ void k_logits(const float* __restrict__ Wlin, const float* __restrict__ blin,
                         float* __restrict__ out) {
    int g = blockIdx.x * blockDim.x + threadIdx.x;
    if (g >= NG) return;
    float gv[16];
#pragma unroll
    for (int q = 0; q < 4; q++) {
        float4 p = g_pool[g * 4 + q];
        gv[q * 4 + 0] = p.x; gv[q * 4 + 1] = p.y;
        gv[q * 4 + 2] = p.z; gv[q * 4 + 3] = p.w;
    }
    float lg[7];
#pragma unroll
    for (int o = 0; o < 7; o++) {
        float acc = __ldg(blin + o);
#pragma unroll
        for (int k = 0; k < 16; k++)
            acc = fmaf(gv[k], __ldg(Wlin + k * 7 + o), acc);
        lg[o] = acc;
    }
    float m = lg[0];
#pragma unroll
    for (int o = 1; o < 7; o++) m = fmaxf(m, lg[o]);
    float s = 0.f;
#pragma unroll
    for (int o = 0; o < 7; o++) s += expf(lg[o] - m);
    float ls = logf(s) + m;
#pragma unroll
    for (int o = 0; o < 7; o++) out[g * 7 + o] = lg[o] - ls;
}

// ---------------------------------------------------------------------------
extern "C" void kernel_launch(void* const* d_in, const int* in_sizes, int n_in,
                              void* d_out, int out_size) {
    int p = 0;
    const float* x     = (const float*)d_in[p]; p++;
    const void*  ei    = d_in[p];
    int twoE = in_sizes[p];
    int E = twoE / 2; p++;
    const void*  batch = d_in[p]; p++;
    if (p < n_in && in_sizes[p] == 1) p++;  // skip scalar num_graphs if present
    const float* W1   = (const float*)d_in[p]; p++;
    const float* b1   = (const float*)d_in[p]; p++;
    const float* W2   = (const float*)d_in[p]; p++;
    const float* b2   = (const float*)d_in[p]; p++;
    const float* Wlin = (const float*)d_in[p]; p++;
    const float* blin = (const float*)d_in[p]; p++;
    float* out = (float*)d_out;

    const int TB = 256;
    int gN  = (NN + TB - 1) / TB;
    int gN4 = (NN * 4 + TB - 1) / TB;
    int gE  = (E + TB - 1) / TB;
    int gIni = (NG * 4 + TB - 1) / TB > gN ? (NG * 4 + TB - 1) / TB : gN;

    k_init   <<<gIni, TB>>>(ei, twoE);
    k_deg    <<<gE,   TB>>>(ei, batch, E);
    k_scanA  <<<NBLK, TB>>>();
    k_scanB  <<<1,    512>>>();
    k_scanC  <<<NBLK, TB>>>();
    k_bucket <<<gE,   TB>>>(ei, E);
    k_hs1    <<<gN,   TB>>>(x, W1);
    k_layer1 <<<gN4,  TB>>>(b1, W2);
    k_layer2 <<<gN4,  TB>>>(b2);
    k_logits <<<(NG + TB - 1) / TB, TB>>>(Wlin, blin, out);
}